// round 9
// baseline (speedup 1.0000x reference)
#include <cuda_runtime.h>
#include <cstdint>

// Masked cumsum along dim 1: out[b,:] = cumsum(where(mask, x, 0))
// B=256 rows, N=131072 cols, fp32 x, int32 mask.
//
// R9: shrink the sync domain. 256 CTAs x 128 threads (4 warps per row),
// chunk = 2048 elems, 64 iterations. The 512-thread barrier in R5 coupled 16
// warps -- one straggler stalled all -- leaving DRAM-issue gaps (DRAM pinned
// at 79%). Here the barrier spans 4 warps, the CTA scan is a 4-entry scalar
// tree (1x LDS.128 + SEL/FADD), and each warp runs 4 ILP shfl-scan chains
// over its contiguous 512-float segment (4 perfectly-coalesced float4/int4
// rounds). 1-deep prefetch split into two 4-load groups; streaming hints;
// double-buffered smem -> ONE barrier per iteration.

#define CS_THREADS 128
#define CS_NWARPS  4
#define CS_ROUNDS  4
#define CS_CHUNK   2048                   // 128 thr * 16 elems
#define CS_NCOLS   131072
#define CS_ITERS   (CS_NCOLS / CS_CHUNK)  // 64

__global__ __launch_bounds__(CS_THREADS)
void masked_cumsum_kernel(const float* __restrict__ x,
                          const int* __restrict__ mask,
                          float* __restrict__ out) {
    __shared__ __align__(16) float shW[2][CS_NWARPS];  // [buf][w] = warp total

    const int row = blockIdx.x;
    const size_t roff4 = (size_t)row * (CS_NCOLS / 4);
    const float4* __restrict__ x4 = reinterpret_cast<const float4*>(x) + roff4;
    const int4*   __restrict__ m4 = reinterpret_cast<const int4*>(mask) + roff4;
    float4*       __restrict__ o4 = reinterpret_cast<float4*>(out) + roff4;

    const int tid  = threadIdx.x;
    const int lane = tid & 31;
    const int warp = tid >> 5;
    // Warp w owns floats [w*512, w*512+512) of each chunk:
    // round r (0..3), lane l -> float4 index w*128 + r*32 + l (coalesced)
    const int wbase = warp * 128 + lane;

    float carry = 0.0f;

    // Prefetch chunk 0
    float4 pa[CS_ROUNDS];
    int4   pm[CS_ROUNDS];
    #pragma unroll
    for (int b = 0; b < CS_ROUNDS; ++b) {
        pa[b] = __ldcs(&x4[wbase + b * 32]);
        pm[b] = __ldcs(&m4[wbase + b * 32]);
    }

    for (int it = 0; it < CS_ITERS; ++it) {
        float4 xa[CS_ROUNDS];
        int4   ma[CS_ROUNDS];
        #pragma unroll
        for (int b = 0; b < CS_ROUNDS; ++b) { xa[b] = pa[b]; ma[b] = pm[b]; }

        const int nb = (it + 1) * (CS_CHUNK / 4) + wbase;
        const bool more = (it + 1 < CS_ITERS);

        // First prefetch group: x
        if (more) {
            #pragma unroll
            for (int b = 0; b < CS_ROUNDS; ++b) pa[b] = __ldcs(&x4[nb + b * 32]);
        }

        // Apply mask (each int32 is 0 or 1) + lane-local inclusive scans
        float v[CS_ROUNDS][4];
        #pragma unroll
        for (int b = 0; b < CS_ROUNDS; ++b) {
            v[b][0] = ma[b].x ? xa[b].x : 0.f;
            v[b][1] = ma[b].y ? xa[b].y : 0.f;
            v[b][2] = ma[b].z ? xa[b].z : 0.f;
            v[b][3] = ma[b].w ? xa[b].w : 0.f;
            v[b][1] += v[b][0];
            v[b][2] += v[b][1];
            v[b][3] += v[b][2];
        }

        // Second prefetch group: mask
        if (more) {
            #pragma unroll
            for (int b = 0; b < CS_ROUNDS; ++b) pm[b] = __ldcs(&m4[nb + b * 32]);
        }

        // 4 independent warp scans (ILP), then chain round totals
        float lexcl[CS_ROUNDS], T[CS_ROUNDS];
        {
            float i0 = v[0][3], i1 = v[1][3], i2 = v[2][3], i3 = v[3][3];
            #pragma unroll
            for (int d = 1; d < 32; d <<= 1) {
                float n0 = __shfl_up_sync(0xffffffffu, i0, d);
                float n1 = __shfl_up_sync(0xffffffffu, i1, d);
                float n2 = __shfl_up_sync(0xffffffffu, i2, d);
                float n3 = __shfl_up_sync(0xffffffffu, i3, d);
                if (lane >= d) { i0 += n0; i1 += n1; i2 += n2; i3 += n3; }
            }
            lexcl[0] = i0 - v[0][3]; lexcl[1] = i1 - v[1][3];
            lexcl[2] = i2 - v[2][3]; lexcl[3] = i3 - v[3][3];
            T[0] = __shfl_sync(0xffffffffu, i0, 31);
            T[1] = __shfl_sync(0xffffffffu, i1, 31);
            T[2] = __shfl_sync(0xffffffffu, i2, 31);
            T[3] = __shfl_sync(0xffffffffu, i3, 31);
        }
        float rExcl[CS_ROUNDS];
        rExcl[0] = 0.f;
        rExcl[1] = T[0];
        rExcl[2] = T[0] + T[1];
        rExcl[3] = rExcl[2] + T[2];
        const float warpTotal = rExcl[3] + T[3];

        const int buf = it & 1;
        if (lane == 0) shW[buf][warp] = warpTotal;
        __syncthreads();

        // 4-entry CTA scan: one LDS.128 + tiny scalar tree (uniform per warp)
        const float4 q = *reinterpret_cast<const float4*>(shW[buf]);
        const float chunkTotal = (q.x + q.y) + (q.z + q.w);
        const float wexcl = (warp > 0 ? q.x : 0.f) +
                            (warp > 1 ? q.y : 0.f) +
                            (warp > 2 ? q.z : 0.f);

        const float base0 = carry + wexcl;
        carry += chunkTotal;

        const int ob = it * (CS_CHUNK / 4) + wbase;
        #pragma unroll
        for (int b = 0; b < CS_ROUNDS; ++b) {
            const float base = base0 + rExcl[b] + lexcl[b];
            float4 o;
            o.x = v[b][0] + base;
            o.y = v[b][1] + base;
            o.z = v[b][2] + base;
            o.w = v[b][3] + base;
            __stcs(&o4[ob + b * 32], o);
        }
        // No trailing barrier: iter i+2's STS to this buf is fenced by iter i+1's bar.
    }
}

extern "C" void kernel_launch(void* const* d_in, const int* in_sizes, int n_in,
                              void* d_out, int out_size) {
    const float* x    = (const float*)d_in[0];
    const int*   mask = (const int*)d_in[1];
    float*       out  = (float*)d_out;
    const int rows = out_size / CS_NCOLS;   // 256
    masked_cumsum_kernel<<<rows, CS_THREADS>>>(x, mask, out);
}

// round 10
// speedup vs baseline: 1.4392x; 1.4392x over previous
#include <cuda_runtime.h>
#include <cstdint>

// Masked cumsum along dim 1: out[b,:] = cumsum(where(mask, x, 0))
// B=256 rows, N=131072 cols, fp32 x, int32 mask.
//
// R5 memory machinery (one CTA per row, 512 thr, chunks of 4096, warp-owned
// contiguous 256-float segments, 2 perfectly-coalesced float4/int4 rounds,
// 1-deep prefetch, streaming hints) with the per-chunk __syncthreads replaced
// by a LAG-1 software pipeline over mbarriers:
//   iter j: prefetch j+1 -> scan chunk j -> lane0 STS total to shW[j&3] +
//   arrive mbar[j&3] (count=16) -> wait mbar[(j-1)&3] (arrived a full
//   iteration ago -> fast-path, no convergence stall) -> CTA-scan chunk j-1's
//   totals -> base-add + store chunk j-1 from saved registers.
// Warps may drift ~1 iteration apart instead of lock-stepping 32x/row.
// 4 smem buffers + 4 mbarriers: overwrite of shW[b] at iter j+4 is ordered
// behind all reads of shW[b] at iter j+1 by the arrive chain (a warp arriving
// at j+4 passed waits at j+3..j+1 in program order; its peers' arrivals at
// j+2 certify their j+1 reads completed).

#define CS_THREADS 512
#define CS_NWARPS  16
#define CS_CHUNK   4096                   // 512 thr * 8 elems
#define CS_NCOLS   131072
#define CS_ITERS   (CS_NCOLS / CS_CHUNK)  // 32

__device__ __forceinline__ unsigned smem_u32(const void* p) {
    unsigned a;
    asm("{ .reg .u64 t; cvta.to.shared.u64 t, %1; cvt.u32.u64 %0, t; }"
        : "=r"(a) : "l"(p));
    return a;
}
__device__ __forceinline__ void mbar_init(unsigned addr, unsigned count) {
    asm volatile("mbarrier.init.shared.b64 [%0], %1;" :: "r"(addr), "r"(count) : "memory");
}
__device__ __forceinline__ void mbar_arrive(unsigned addr) {
    asm volatile("mbarrier.arrive.release.cta.shared::cta.b64 _, [%0];" :: "r"(addr) : "memory");
}
__device__ __forceinline__ void mbar_wait(unsigned addr, unsigned parity) {
    unsigned done;
    asm volatile(
        "{\n\t.reg .pred p;\n\t"
        "mbarrier.try_wait.parity.acquire.cta.shared::cta.b64 p, [%1], %2;\n\t"
        "selp.b32 %0, 1, 0, p;\n\t}"
        : "=r"(done) : "r"(addr), "r"(parity) : "memory");
    while (!done) {
        asm volatile(
            "{\n\t.reg .pred p;\n\t"
            "mbarrier.try_wait.parity.acquire.cta.shared::cta.b64 p, [%1], %2, 0x989680;\n\t"
            "selp.b32 %0, 1, 0, p;\n\t}"
            : "=r"(done) : "r"(addr), "r"(parity) : "memory");
    }
}

__global__ __launch_bounds__(CS_THREADS, 2)
void masked_cumsum_kernel(const float* __restrict__ x,
                          const int* __restrict__ mask,
                          float* __restrict__ out) {
    __shared__ float shW[4][CS_NWARPS];                    // [buf][w] = warp total
    __shared__ __align__(8) unsigned long long mbar[4];

    const int row = blockIdx.x;
    const size_t roff4 = (size_t)row * (CS_NCOLS / 4);
    const float4* __restrict__ x4 = reinterpret_cast<const float4*>(x) + roff4;
    const int4*   __restrict__ m4 = reinterpret_cast<const int4*>(mask) + roff4;
    float4*       __restrict__ o4 = reinterpret_cast<float4*>(out) + roff4;

    const int tid  = threadIdx.x;
    const int lane = tid & 31;
    const int warp = tid >> 5;
    const int wbase = warp * 64 + lane;   // float4 index of warp segment start

    const unsigned mb0 = smem_u32(&mbar[0]);
    if (tid == 0) {
        #pragma unroll
        for (int b = 0; b < 4; ++b) mbar_init(mb0 + b * 8, CS_NWARPS);
    }
    __syncthreads();   // one-time: mbarrier init visibility

    unsigned ph = 0;       // bit b = expected parity of mbar[b]
    float carry = 0.0f;

    // Saved (lag-1) chunk state: values with lexcl/T0 pre-folded -> add base0 only
    float sv[8];

    // Prefetch chunk 0
    float4 pa0 = __ldcs(&x4[wbase]);
    float4 pa1 = __ldcs(&x4[wbase + 32]);
    int4   pm0 = __ldcs(&m4[wbase]);
    int4   pm1 = __ldcs(&m4[wbase + 32]);

    for (int it = 0; it < CS_ITERS; ++it) {
        const float4 xa0 = pa0, xa1 = pa1;
        const int4   ma0 = pm0, ma1 = pm1;
        if (it + 1 < CS_ITERS) {
            const int nb = (it + 1) * (CS_CHUNK / 4) + wbase;
            pa0 = __ldcs(&x4[nb]);
            pa1 = __ldcs(&x4[nb + 32]);
            pm0 = __ldcs(&m4[nb]);
            pm1 = __ldcs(&m4[nb + 32]);
        }

        // Mask + lane-local inclusive scans (2 ILP rounds)
        float v[2][4];
        v[0][0] = ma0.x ? xa0.x : 0.f; v[0][1] = ma0.y ? xa0.y : 0.f;
        v[0][2] = ma0.z ? xa0.z : 0.f; v[0][3] = ma0.w ? xa0.w : 0.f;
        v[1][0] = ma1.x ? xa1.x : 0.f; v[1][1] = ma1.y ? xa1.y : 0.f;
        v[1][2] = ma1.z ? xa1.z : 0.f; v[1][3] = ma1.w ? xa1.w : 0.f;
        #pragma unroll
        for (int b = 0; b < 2; ++b)
            #pragma unroll
            for (int i = 1; i < 4; ++i) v[b][i] += v[b][i - 1];

        // 2 ILP warp scans
        float lexcl0, lexcl1, T0, T1;
        {
            float ia = v[0][3], ib = v[1][3];
            #pragma unroll
            for (int d = 1; d < 32; d <<= 1) {
                float na = __shfl_up_sync(0xffffffffu, ia, d);
                float nb = __shfl_up_sync(0xffffffffu, ib, d);
                if (lane >= d) { ia += na; ib += nb; }
            }
            lexcl0 = ia - v[0][3];
            lexcl1 = ib - v[1][3];
            T0 = __shfl_sync(0xffffffffu, ia, 31);
            T1 = __shfl_sync(0xffffffffu, ib, 31);
        }

        // Publish this chunk's warp total: STS + arrive (lane 0 only, count=16)
        const int bufW = it & 3;
        if (lane == 0) {
            shW[bufW][warp] = T0 + T1;
            mbar_arrive(mb0 + bufW * 8);
        }

        // Finalize chunk it-1 (its totals arrived a full iteration ago)
        if (it > 0) {
            const int bR = (it - 1) & 3;
            mbar_wait(mb0 + bR * 8, (ph >> bR) & 1u);
            ph ^= (1u << bR);

            float w = (lane < CS_NWARPS) ? shW[bR][lane] : 0.f;
            float wincl = w;
            #pragma unroll
            for (int d = 1; d < CS_NWARPS; d <<= 1) {
                float n = __shfl_up_sync(0xffffffffu, wincl, d);
                if (lane >= d) wincl += n;
            }
            const float wexcl      = __shfl_sync(0xffffffffu, wincl, warp) -
                                     __shfl_sync(0xffffffffu, w,     warp);
            const float chunkTotal = __shfl_sync(0xffffffffu, wincl, CS_NWARPS - 1);
            const float base0 = carry + wexcl;
            carry += chunkTotal;

            const int ob = (it - 1) * (CS_CHUNK / 4) + wbase;
            float4 oa, obv;
            oa.x  = sv[0] + base0; oa.y  = sv[1] + base0;
            oa.z  = sv[2] + base0; oa.w  = sv[3] + base0;
            obv.x = sv[4] + base0; obv.y = sv[5] + base0;
            obv.z = sv[6] + base0; obv.w = sv[7] + base0;
            __stcs(&o4[ob],      oa);
            __stcs(&o4[ob + 32], obv);
        }

        // Save current chunk with lexcl/T0 folded (add base0 only at store time)
        sv[0] = v[0][0] + lexcl0; sv[1] = v[0][1] + lexcl0;
        sv[2] = v[0][2] + lexcl0; sv[3] = v[0][3] + lexcl0;
        const float fB = lexcl1 + T0;
        sv[4] = v[1][0] + fB; sv[5] = v[1][1] + fB;
        sv[6] = v[1][2] + fB; sv[7] = v[1][3] + fB;
    }

    // Tail: finalize chunk 31
    {
        const int bR = (CS_ITERS - 1) & 3;
        mbar_wait(mb0 + bR * 8, (ph >> bR) & 1u);

        float w = (lane < CS_NWARPS) ? shW[bR][lane] : 0.f;
        float wincl = w;
        #pragma unroll
        for (int d = 1; d < CS_NWARPS; d <<= 1) {
            float n = __shfl_up_sync(0xffffffffu, wincl, d);
            if (lane >= d) wincl += n;
        }
        const float wexcl = __shfl_sync(0xffffffffu, wincl, warp) -
                            __shfl_sync(0xffffffffu, w,     warp);
        const float base0 = carry + wexcl;

        const int ob = (CS_ITERS - 1) * (CS_CHUNK / 4) + wbase;
        float4 oa, obv;
        oa.x  = sv[0] + base0; oa.y  = sv[1] + base0;
        oa.z  = sv[2] + base0; oa.w  = sv[3] + base0;
        obv.x = sv[4] + base0; obv.y = sv[5] + base0;
        obv.z = sv[6] + base0; obv.w = sv[7] + base0;
        __stcs(&o4[ob],      oa);
        __stcs(&o4[ob + 32], obv);
    }
}

extern "C" void kernel_launch(void* const* d_in, const int* in_sizes, int n_in,
                              void* d_out, int out_size) {
    const float* x    = (const float*)d_in[0];
    const int*   mask = (const int*)d_in[1];
    float*       out  = (float*)d_out;
    const int rows = out_size / CS_NCOLS;   // 256
    masked_cumsum_kernel<<<rows, CS_THREADS>>>(x, mask, out);
}